// round 9
// baseline (speedup 1.0000x reference)
#include <cuda_runtime.h>
#include <cstdint>

// ============================================================================
// OneHotEncoding — single kernel, ZERO grid barriers (R8 lesson: grid-wide
// barrier phases serialized the fused kernel; occupancy didn't matter).
// Every block is self-sufficient: it probes its own distance upper bounds,
// builds its own smem candidate table, streams its share of points, and
// merges via rare global atomics. Last-finishing block finalizes.
//
// Output layout (float32):
//   [0, 4L)            input_tensor: per point (x, y, z, one_hot)
//   [4L, 4L+3B)        closest_points [B,3]
//   [4L+3B, 4L+4B)     min_index as float [B]
//
// Global merge key: ~((u64)d2bits<<32 | idx), merged with atomicMax.
//   - complement => zero-initialized .bss state IS the identity (no init pass)
//   - max of complement == min of (d2, idx) => first-index tie-break
//   - finalize resets to 0 => graph-replay deterministic
//
// Per-block candidate table (16^3 cells): receiver r's box [r-UB, r+UB]^3
// covers r's true NN (UB is an exact distance to a real sample point).
// Cells with >K listed receivers get sentinel 255 => brute-force all B
// (probability ~5e-4 of cells) — correctness is unconditional.
// ============================================================================

#define GC       16
#define CELLS    (GC * GC * GC)        // 4096
#define MAXB     128
#define GRID     152
#define THREADS  1024
#define KCAP     5                     // candidate list slots per cell
#define PROBE_N  512                   // sample points for UB probe

__device__ unsigned long long g_best[MAXB];   // complemented keys; 0 = identity
__device__ unsigned int       g_done;         // zero-init; self-resetting

__device__ __forceinline__ int cell_clamp(int c) {
    c = c < 0 ? 0 : c;
    return c > GC - 1 ? GC - 1 : c;
}
__device__ __forceinline__ int cell_of(float x) {
    return cell_clamp(__float2int_rd(x * (float)GC));
}

// ---------------------------------------------------------------------------
__global__ void __launch_bounds__(THREADS, 1)
fused_kernel(const float* __restrict__ pts, const float* __restrict__ recv,
             float* __restrict__ out, int L, int B)
{
    const int tid  = threadIdx.x;
    const int lane = tid & 31;
    const int wid  = tid >> 5;
    const int bid  = blockIdx.x;

    __shared__ float srx[MAXB], sry[MAXB], srz[MAXB];
    __shared__ float s_ub[MAXB];                       // min d2 per receiver
    __shared__ unsigned char s_list[CELLS * KCAP];     // 20 KB
    __shared__ unsigned char s_cnt[CELLS];             // 4 KB (255 = overflow)
    // scratch: probe SoA (6KB) -> cnt32 (16KB) -> tile SoA (12KB)
    __shared__ __align__(16) unsigned char s_scratch[16384];

    // ---- stage receivers ----
    if (tid < B) {
        srx[tid] = recv[3 * tid + 0];
        sry[tid] = recv[3 * tid + 1];
        srz[tid] = recv[3 * tid + 2];
    }

    // ---- stage probe sample points (SoA) into scratch ----
    float* s_px = reinterpret_cast<float*>(s_scratch);
    float* s_py = s_px + PROBE_N;
    float* s_pz = s_py + PROBE_N;
    const int n  = (L < PROBE_N) ? L : PROBE_N;
    const int n3 = n * 3;
#pragma unroll
    for (int j = 0; j < 2; ++j) {
        int e = tid + j * THREADS;                 // [0, 1536)
        if (e < PROBE_N * 3) {
            float v = (e < n3) ? pts[e] : 1.0e30f;
            int p = e / 3, c = e - p * 3;
            if      (c == 0) s_px[p] = v;
            else if (c == 1) s_py[p] = v;
            else             s_pz[p] = v;
        }
    }
    __syncthreads();

    // ---- UB probe: warp wid owns receivers [4*wid, 4*wid+4) ----
    {
        const int rbase = wid * 4;
        float rx[4], ry[4], rz[4], bd[4];
#pragma unroll
        for (int k = 0; k < 4; ++k) {
            int rb = rbase + k;
            rx[k] = (rb < B) ? srx[rb] : 0.f;
            ry[k] = (rb < B) ? sry[rb] : 0.f;
            rz[k] = (rb < B) ? srz[rb] : 0.f;
            bd[k] = 3.4e38f;
        }
#pragma unroll 4
        for (int j = 0; j < PROBE_N / 32; ++j) {
            float px = s_px[lane + 32 * j];
            float py = s_py[lane + 32 * j];
            float pz = s_pz[lane + 32 * j];
#pragma unroll
            for (int k = 0; k < 4; ++k) {
                float dx = px - rx[k];
                float dy = py - ry[k];
                float dz = pz - rz[k];
                float d2 = dx * dx + dy * dy + dz * dz;
                bd[k] = fminf(bd[k], d2);
            }
        }
#pragma unroll
        for (int k = 0; k < 4; ++k) {
#pragma unroll
            for (int m = 16; m > 0; m >>= 1)
                bd[k] = fminf(bd[k], __shfl_xor_sync(0xffffffffu, bd[k], m));
            if (lane == 0 && (rbase + k) < B) s_ub[rbase + k] = bd[k];
        }
    }
    __syncthreads();

    // ---- zero cnt32 (scratch reuse), then build lists receiver-major ----
    unsigned int* cnt32 = reinterpret_cast<unsigned int*>(s_scratch);
#pragma unroll
    for (int j = 0; j < CELLS / THREADS; ++j) cnt32[tid + j * THREADS] = 0u;
    __syncthreads();

    if (tid < B) {
        float ub = sqrtf(s_ub[tid]) * 1.0001f + 1e-7f;   // ulp guard
        float rx = srx[tid], ry = sry[tid], rz = srz[tid];
        int lx = cell_of(rx - ub), hx = cell_of(rx + ub);
        int ly = cell_of(ry - ub), hy = cell_of(ry + ub);
        int lz = cell_of(rz - ub), hz = cell_of(rz + ub);
        for (int zz = lz; zz <= hz; ++zz)
            for (int yy = ly; yy <= hy; ++yy)
                for (int xx = lx; xx <= hx; ++xx) {
                    int c = (zz * GC + yy) * GC + xx;
                    unsigned int pos = atomicAdd(&cnt32[c], 1u);
                    if (pos < KCAP) s_list[c * KCAP + pos] = (unsigned char)tid;
                }
    }
    __syncthreads();

    // ---- compact counts to u8 with overflow sentinel ----
#pragma unroll
    for (int j = 0; j < CELLS / THREADS; ++j) {
        int c = tid + j * THREADS;
        unsigned int v = cnt32[c];
        s_cnt[c] = (v > KCAP) ? (unsigned char)255 : (unsigned char)v;
    }
    __syncthreads();

    // ---- streaming pass: smem-staged tiles, coalesced in and out ----
    float* t_x = reinterpret_cast<float*>(s_scratch);
    float* t_y = t_x + THREADS;
    float* t_z = t_y + THREADS;
    const int nTiles = (L + THREADS - 1) / THREADS;
    const int L3 = L * 3;

    for (int tile = bid; tile < nTiles; tile += GRID) {
        const int base = tile * THREADS;
        __syncthreads();                 // previous tile fully consumed
#pragma unroll
        for (int j = 0; j < 3; ++j) {
            int e  = tid + j * THREADS;
            int ge = base * 3 + e;
            float v = (ge < L3) ? pts[ge] : 2.0f;    // pad: out of domain
            int p = e / 3, c = e - p * 3;
            if      (c == 0) t_x[p] = v;
            else if (c == 1) t_y[p] = v;
            else             t_z[p] = v;
        }
        __syncthreads();

        const int p = base + tid;
        if (p < L) {
            float x = t_x[tid], y = t_y[tid], z = t_z[tid];
            *reinterpret_cast<float4*>(out + 4 * (size_t)p) =
                make_float4(x, y, z, 0.0f);          // coalesced float4 store

            int c = (cell_of(z) * GC + cell_of(y)) * GC + cell_of(x);
            unsigned int cn = s_cnt[c];
            if (cn) {
                int lim  = (cn == 255u) ? B : (int)cn;
                bool all = (cn == 255u);
                for (int k = 0; k < lim; ++k) {
                    int r = all ? k : (int)s_list[c * KCAP + k];
                    float dx = x - srx[r];
                    float dy = y - sry[r];
                    float dz = z - srz[r];
                    float d2 = dx * dx + dy * dy + dz * dz;
                    unsigned long long key =
                        ~((((unsigned long long)__float_as_uint(d2)) << 32) |
                          (unsigned long long)(unsigned int)p);
                    // plain read may be stale-LOW (monotone increasing) => a
                    // skipped atomic was non-improving; atomicMax authoritative
                    if (key > g_best[r]) atomicMax(&g_best[r], key);
                }
            }
        }
    }

    // ---- last-finishing block finalizes ----
    __threadfence();
    __syncthreads();
    __shared__ bool is_last;
    if (tid == 0) is_last = (atomicAdd(&g_done, 1u) == GRID - 1);
    __syncthreads();
    if (!is_last) return;

    if (tid < B) {
        // authoritative read (atomicMax with identity 0 leaves value intact)
        unsigned long long key = atomicMax(&g_best[tid], 0ull);
        unsigned int idx = ~((unsigned int)(key & 0xffffffffull));
        float* cp = out + 4 * (size_t)L;
        cp[3 * tid + 0] = pts[3 * idx + 0];
        cp[3 * tid + 1] = pts[3 * idx + 1];
        cp[3 * tid + 2] = pts[3 * idx + 2];
        out[4 * (size_t)L + 3 * B + tid] = (float)idx;   // min_index as float
        out[4 * (size_t)idx + 3] = 1.0f;                 // one-hot scatter
        g_best[tid] = 0ull;                              // reset for next replay
    }
    if (tid == 0) {
        if (B > 1) out[3] = 1.0f;        // reference quirk: index 0 also set
        g_done = 0u;                     // reset for next replay
    }
}

// ---------------------------------------------------------------------------
extern "C" void kernel_launch(void* const* d_in, const int* in_sizes, int n_in,
                              void* d_out, int out_size)
{
    const float* pts  = (const float*)d_in[0];   // mesh_3D flattened [L,3]
    const float* recv = (const float*)d_in[1];   // receiver_pos [B,3]
    float* out = (float*)d_out;

    int L = in_sizes[0] / 3;   // 1,000,000
    int B = in_sizes[1] / 3;   // 128

    fused_kernel<<<GRID, THREADS>>>(pts, recv, out, L, B);
}

// round 10
// speedup vs baseline: 3.5102x; 3.5102x over previous
#include <cuda_runtime.h>
#include <cstdint>

// ============================================================================
// OneHotEncoding — single kernel, zero grid barriers, BLOCK-LOCAL argmin.
//
// R9 lesson: guarding global atomics with plain L1 reads of g_best fails —
// L1 is never invalidated by remote atomics, the guard stays at the identity
// forever, and ~850K atomicMax onto 128 addresses serialize in the LTS
// (~32cyc/op/address) => 110us. Fix: accumulate per-block bests in SHARED
// memory (coherent in-block, cheap atomics), seeded by the block's own probe,
// and merge to global exactly once per block (152*128 atomics total).
//
// Output layout (float32):
//   [0, 4L)            input_tensor: per point (x, y, z, one_hot)
//   [4L, 4L+3B)        closest_points [B,3]
//   [4L+3B, 4L+4B)     min_index as float [B]
//
// Merge key: ~((u64)d2bits<<32 | idx), combined with max.
//   - zero-initialized .bss g_best IS the identity (no init pass)
//   - max of complement == min (d2, idx) => first-index tie-break
//   - probe seed ~(probe_d2<<32 | 0xFFFFFFFF) is provably below the true
//     winner's key (true d2 <= probe d2; real idx < 0xFFFFFFFF) and above
//     nothing valid, so it only filters, never decides.
//   - finalize resets g_best/g_done to 0 => graph-replay deterministic.
//
// Candidate table: receiver r's box [r-UB, r+UB]^3 (UB = exact distance to a
// real sampled point) covers r's true NN. Cells with >KCAP receivers get
// sentinel 255 => brute-force all B for points there. Unconditionally correct.
// ============================================================================

#define GC       16
#define CELLS    (GC * GC * GC)        // 4096
#define MAXB     128
#define GRID     152
#define THREADS  1024
#define KCAP     5                     // candidate list slots per cell
#define PROBE_N  1024                  // sample points for UB probe

__device__ unsigned long long g_best[MAXB];   // complemented keys; 0 = identity
__device__ unsigned int       g_done;         // zero-init; self-resetting

__device__ __forceinline__ int cell_clamp(int c) {
    c = c < 0 ? 0 : c;
    return c > GC - 1 ? GC - 1 : c;
}
__device__ __forceinline__ int cell_of(float x) {
    return cell_clamp(__float2int_rd(x * (float)GC));
}

// ---------------------------------------------------------------------------
__global__ void __launch_bounds__(THREADS, 1)
fused_kernel(const float* __restrict__ pts, const float* __restrict__ recv,
             float* __restrict__ out, int L, int B)
{
    const int tid  = threadIdx.x;
    const int lane = tid & 31;
    const int wid  = tid >> 5;
    const int bid  = blockIdx.x;

    __shared__ float srx[MAXB], sry[MAXB], srz[MAXB];
    __shared__ float s_ub[MAXB];                       // probe min d2 per recv
    __shared__ unsigned long long s_best[MAXB];        // block-local keys
    __shared__ unsigned char s_list[CELLS * KCAP];     // 20 KB
    __shared__ unsigned char s_cnt[CELLS];             // 4 KB (255 = overflow)
    // scratch: probe SoA (12KB) -> cnt32 (16KB) -> tile SoA (12KB)
    __shared__ __align__(16) unsigned char s_scratch[16384];

    // ---- stage receivers ----
    if (tid < B) {
        srx[tid] = recv[3 * tid + 0];
        sry[tid] = recv[3 * tid + 1];
        srz[tid] = recv[3 * tid + 2];
    }

    // ---- stage probe sample points (SoA) into scratch ----
    float* s_px = reinterpret_cast<float*>(s_scratch);
    float* s_py = s_px + PROBE_N;
    float* s_pz = s_py + PROBE_N;
    const int n  = (L < PROBE_N) ? L : PROBE_N;
    const int n3 = n * 3;
#pragma unroll
    for (int j = 0; j < 3; ++j) {
        int e = tid + j * THREADS;                 // [0, 3072)
        float v = (e < n3) ? pts[e] : 1.0e30f;
        int p = e / 3, c = e - p * 3;
        if      (c == 0) s_px[p] = v;
        else if (c == 1) s_py[p] = v;
        else             s_pz[p] = v;
    }
    __syncthreads();

    // ---- UB probe: warp wid owns receivers [4*wid, 4*wid+4) ----
    {
        const int rbase = wid * 4;
        float rx[4], ry[4], rz[4], bd[4];
#pragma unroll
        for (int k = 0; k < 4; ++k) {
            int rb = rbase + k;
            rx[k] = (rb < B) ? srx[rb] : 0.f;
            ry[k] = (rb < B) ? sry[rb] : 0.f;
            rz[k] = (rb < B) ? srz[rb] : 0.f;
            bd[k] = 3.4e38f;
        }
#pragma unroll 4
        for (int j = 0; j < PROBE_N / 32; ++j) {
            float px = s_px[lane + 32 * j];
            float py = s_py[lane + 32 * j];
            float pz = s_pz[lane + 32 * j];
#pragma unroll
            for (int k = 0; k < 4; ++k) {
                float dx = px - rx[k];
                float dy = py - ry[k];
                float dz = pz - rz[k];
                float d2 = dx * dx + dy * dy + dz * dz;
                bd[k] = fminf(bd[k], d2);
            }
        }
#pragma unroll
        for (int k = 0; k < 4; ++k) {
#pragma unroll
            for (int m = 16; m > 0; m >>= 1)
                bd[k] = fminf(bd[k], __shfl_xor_sync(0xffffffffu, bd[k], m));
            if (lane == 0 && (rbase + k) < B) {
                s_ub[rbase + k] = bd[k];
                // seed: below the true winner (d2 >= true, idx field maximal)
                s_best[rbase + k] =
                    ~((((unsigned long long)__float_as_uint(bd[k])) << 32) |
                      0xFFFFFFFFull);
            }
        }
    }
    __syncthreads();

    // ---- zero cnt32 (scratch reuse), then build lists receiver-major ----
    unsigned int* cnt32 = reinterpret_cast<unsigned int*>(s_scratch);
#pragma unroll
    for (int j = 0; j < CELLS / THREADS; ++j) cnt32[tid + j * THREADS] = 0u;
    __syncthreads();

    if (tid < B) {
        float ub = sqrtf(s_ub[tid]) * 1.0001f + 1e-7f;   // ulp guard
        float rx = srx[tid], ry = sry[tid], rz = srz[tid];
        int lx = cell_of(rx - ub), hx = cell_of(rx + ub);
        int ly = cell_of(ry - ub), hy = cell_of(ry + ub);
        int lz = cell_of(rz - ub), hz = cell_of(rz + ub);
        for (int zz = lz; zz <= hz; ++zz)
            for (int yy = ly; yy <= hy; ++yy)
                for (int xx = lx; xx <= hx; ++xx) {
                    int c = (zz * GC + yy) * GC + xx;
                    unsigned int pos = atomicAdd(&cnt32[c], 1u);
                    if (pos < KCAP) s_list[c * KCAP + pos] = (unsigned char)tid;
                }
    }
    __syncthreads();

    // ---- compact counts to u8 with overflow sentinel ----
#pragma unroll
    for (int j = 0; j < CELLS / THREADS; ++j) {
        int c = tid + j * THREADS;
        unsigned int v = cnt32[c];
        s_cnt[c] = (v > KCAP) ? (unsigned char)255 : (unsigned char)v;
    }
    __syncthreads();

    // ---- streaming pass: smem-staged tiles, coalesced in and out ----
    float* t_x = reinterpret_cast<float*>(s_scratch);
    float* t_y = t_x + THREADS;
    float* t_z = t_y + THREADS;
    const int nTiles = (L + THREADS - 1) / THREADS;
    const int L3 = L * 3;

    for (int tile = bid; tile < nTiles; tile += GRID) {
        const int base = tile * THREADS;
        __syncthreads();                 // previous tile fully consumed
#pragma unroll
        for (int j = 0; j < 3; ++j) {
            int e  = tid + j * THREADS;
            int ge = base * 3 + e;
            float v = (ge < L3) ? pts[ge] : 2.0f;    // pad: out of domain
            int p = e / 3, c = e - p * 3;
            if      (c == 0) t_x[p] = v;
            else if (c == 1) t_y[p] = v;
            else             t_z[p] = v;
        }
        __syncthreads();

        const int p = base + tid;
        if (p < L) {
            float x = t_x[tid], y = t_y[tid], z = t_z[tid];
            *reinterpret_cast<float4*>(out + 4 * (size_t)p) =
                make_float4(x, y, z, 0.0f);          // coalesced float4 store

            int c = (cell_of(z) * GC + cell_of(y)) * GC + cell_of(x);
            unsigned int cn = s_cnt[c];
            if (cn) {
                int lim  = (cn == 255u) ? B : (int)cn;
                bool all = (cn == 255u);
                for (int k = 0; k < lim; ++k) {
                    int r = all ? k : (int)s_list[c * KCAP + k];
                    float dx = x - srx[r];
                    float dy = y - sry[r];
                    float dz = z - srz[r];
                    float d2 = dx * dx + dy * dy + dz * dz;
                    unsigned long long key =
                        ~((((unsigned long long)__float_as_uint(d2)) << 32) |
                          (unsigned long long)(unsigned int)p);
                    // LDS guard is block-coherent; smem atomic authoritative
                    if (key > s_best[r]) atomicMax(&s_best[r], key);
                }
            }
        }
    }
    __syncthreads();

    // ---- one global merge per block (<=128 atomics) ----
    if (tid < B) {
        unsigned long long k = s_best[tid];
        // skip merge if the seed never improved AND it can't win anyway:
        // always merge — 128 atomics/block is cheap and unconditional-correct.
        atomicMax(&g_best[tid], k);
    }

    // ---- last-finishing block finalizes ----
    __threadfence();
    __syncthreads();
    __shared__ bool is_last;
    if (tid == 0) is_last = (atomicAdd(&g_done, 1u) == GRID - 1);
    __syncthreads();
    if (!is_last) return;

    if (tid < B) {
        // authoritative read (atomicMax with identity 0 leaves value intact)
        unsigned long long key = atomicMax(&g_best[tid], 0ull);
        unsigned int idx = ~((unsigned int)(key & 0xffffffffull));
        float* cp = out + 4 * (size_t)L;
        cp[3 * tid + 0] = pts[3 * idx + 0];
        cp[3 * tid + 1] = pts[3 * idx + 1];
        cp[3 * tid + 2] = pts[3 * idx + 2];
        out[4 * (size_t)L + 3 * B + tid] = (float)idx;   // min_index as float
        out[4 * (size_t)idx + 3] = 1.0f;                 // one-hot scatter
        g_best[tid] = 0ull;                              // reset for next replay
    }
    if (tid == 0) {
        if (B > 1) out[3] = 1.0f;        // reference quirk: index 0 also set
        g_done = 0u;                     // reset for next replay
    }
}

// ---------------------------------------------------------------------------
extern "C" void kernel_launch(void* const* d_in, const int* in_sizes, int n_in,
                              void* d_out, int out_size)
{
    const float* pts  = (const float*)d_in[0];   // mesh_3D flattened [L,3]
    const float* recv = (const float*)d_in[1];   // receiver_pos [B,3]
    float* out = (float*)d_out;

    int L = in_sizes[0] / 3;   // 1,000,000
    int B = in_sizes[1] / 3;   // 128

    fused_kernel<<<GRID, THREADS>>>(pts, recv, out, L, B);
}